// round 4
// baseline (speedup 1.0000x reference)
#include <cuda_runtime.h>
#include <cuda_bf16.h>
#include <cstdint>
#include <cstddef>

// Problem constants
#define BATCH 8
#define NV    12000
#define NS    9
#define MTOT  (BATCH * NV)   // 96000
#define NPART (MTOT / 128)   // 750 m-blocks -> stats partials per layer

// Scratch (device globals; no allocation allowed)
__device__ float g_bufA[(size_t)MTOT * 256];   // 98.3 MB
__device__ float g_bufB[(size_t)MTOT * 128];   // 49.2 MB
__device__ float g_psum[NPART * 256];
__device__ float g_psq [NPART * 256];
__device__ float g_scale[256];
__device__ float g_shift[256];
__device__ float g_hmax[BATCH * 256];
__device__ int   g_is64;

// ---------------------------------------------------------------------------
// Detect whether the spiral index tensor is int64 or int32.
// If int64: every 8-byte word is a valid index in [0, NV).
// If int32: the int64 view combines two random indices -> huge values.
// ---------------------------------------------------------------------------
__global__ void detect64_kernel(const long long* __restrict__ p) {
    bool ok = true;
    for (int i = threadIdx.x; i < 2048; i += 256) {
        long long v = p[i];
        if (v < 0 || v >= NV) ok = false;
    }
    int all = __syncthreads_and(ok ? 1 : 0);
    if (threadIdx.x == 0) g_is64 = all;
}

// ---------------------------------------------------------------------------
// Gather-fused SGEMM with fused BN-apply on input (NORM) and fused BN stats
// on output: y[m, n] = sum_k act(feat)[m, k] * w[n, k]
// feat[m, s*CIN + c] = src[(b*NV + spir[m, s]) * CIN + c], m = b*NV + v
// act(v) = NORM ? relu(v * scale[c] + shift[c]) : v
// Conv bias is intentionally dropped: BatchNorm's mean subtraction cancels it.
// Tiling: BM=128, BNT in {64,128}, BK=16; 256 threads; 8 x (BNT/16) microtile.
// As stored transposed [BK][BM+4]; VEC path register-stages the next tile's
// global loads before computing the current tile (latency hiding).
// Per-block column sum/sumsq partials written to psum/psq (deterministic).
// ---------------------------------------------------------------------------
#define BM 128
#define BK 16
#define AS_STRIDE (BM + 4)   // 132: 16B-aligned rows, reduced STS conflicts

template <int CIN, bool VEC, int BNT, bool NORM>
__global__ __launch_bounds__(256)
void gemm_gather_kernel(const float* __restrict__ src,
                        const void* __restrict__ spir_raw,
                        const float* __restrict__ w,
                        const float* __restrict__ scale,
                        const float* __restrict__ shift,
                        float* __restrict__ y,
                        float* __restrict__ psum,
                        float* __restrict__ psq,
                        int N) {
    constexpr int K   = NS * CIN;
    constexpr int TN  = BNT / 16;        // columns per thread (4 or 8)
    constexpr int TG  = TN / 4;          // float4 groups per thread
    constexpr int NBB = (BK * BNT) / (4 * 256);  // B float4s per thread (1 or 2)
    __shared__ float As[BK * AS_STRIDE];
    __shared__ float Bs[BK * BNT];
    __shared__ int   sidx[BM][NS];       // pre-scaled row base: (b*NV + idx)*CIN
    __shared__ __align__(16) float s_sc[CIN];
    __shared__ __align__(16) float s_sh[CIN];

    const int tid = threadIdx.x;
    const int tx = tid & 15;             // n-dim
    const int ty = tid >> 4;             // m-dim
    const int m0 = blockIdx.x * BM;
    const int n0 = blockIdx.y * BNT;

    // Stage BN params for the input activation
    if constexpr (NORM) {
        for (int i = tid; i < CIN; i += 256) {
            s_sc[i] = scale[i];
            s_sh[i] = shift[i];
        }
    }

    // Resolve spiral indices for this row tile
    {
        const long long* s64 = (const long long*)spir_raw;
        const int*       s32 = (const int*)spir_raw;
        const int is64 = g_is64;
        for (int j = tid; j < BM * NS; j += 256) {
            int m = j / NS, s = j - m * NS;
            int gm = m0 + m;
            int b = gm / NV;
            long long e = is64 ? s64[(size_t)gm * NS + s]
                               : (long long)s32[(size_t)gm * NS + s];
            sidx[m][s] = (b * NV + (int)e) * CIN;
        }
    }
    __syncthreads();

    // Apply BN + ReLU to a gathered float4 at channel base c (c % 4 == 0)
    auto act4 = [&](float4 v, int c) -> float4 {
        if constexpr (NORM) {
            float4 sc4 = *reinterpret_cast<const float4*>(&s_sc[c]);
            float4 sh4 = *reinterpret_cast<const float4*>(&s_sh[c]);
            v.x = fmaxf(fmaf(v.x, sc4.x, sh4.x), 0.f);
            v.y = fmaxf(fmaf(v.y, sc4.y, sh4.y), 0.f);
            v.z = fmaxf(fmaf(v.z, sc4.z, sh4.z), 0.f);
            v.w = fmaxf(fmaf(v.w, sc4.w, sh4.w), 0.f);
        }
        return v;
    };

    float acc[8][TN];
#pragma unroll
    for (int i = 0; i < 8; i++)
#pragma unroll
        for (int j = 0; j < TN; j++) acc[i][j] = 0.f;

    if constexpr (VEC) {
        // ---------------- software-pipelined mainloop ----------------
        float4 pa[2], pbv[NBB];

        // prefetch k0 = 0
        {
#pragma unroll
            for (int j = 0; j < 2; j++) {
                int i = tid + j * 256;       // 0..511
                int m = i >> 2, kq = i & 3;
                int k = kq * 4;
                int s = k / CIN, c = k - s * CIN;
                pa[j] = act4(*reinterpret_cast<const float4*>(src + sidx[m][s] + c), c);
            }
#pragma unroll
            for (int j = 0; j < NBB; j++) {
                int i = tid + j * 256;
                int n = i >> 2, kq = i & 3;
                pbv[j] = *reinterpret_cast<const float4*>(
                    w + (size_t)(n0 + n) * K + kq * 4);
            }
        }

        for (int k0 = 0; k0 < K; k0 += BK) {
            // ---- store staged tile to SMEM ----
#pragma unroll
            for (int j = 0; j < 2; j++) {
                int i = tid + j * 256;
                int m = i >> 2, kq = i & 3;
                As[(kq * 4 + 0) * AS_STRIDE + m] = pa[j].x;
                As[(kq * 4 + 1) * AS_STRIDE + m] = pa[j].y;
                As[(kq * 4 + 2) * AS_STRIDE + m] = pa[j].z;
                As[(kq * 4 + 3) * AS_STRIDE + m] = pa[j].w;
            }
#pragma unroll
            for (int j = 0; j < NBB; j++) {
                int i = tid + j * 256;
                int n = i >> 2, kq = i & 3;
                Bs[(kq * 4 + 0) * BNT + n] = pbv[j].x;
                Bs[(kq * 4 + 1) * BNT + n] = pbv[j].y;
                Bs[(kq * 4 + 2) * BNT + n] = pbv[j].z;
                Bs[(kq * 4 + 3) * BNT + n] = pbv[j].w;
            }
            __syncthreads();

            // ---- issue next tile's global loads (fly under compute) ----
            const int kn = k0 + BK;
            if (kn < K) {
#pragma unroll
                for (int j = 0; j < 2; j++) {
                    int i = tid + j * 256;
                    int m = i >> 2, kq = i & 3;
                    int k = kn + kq * 4;
                    int s = k / CIN, c = k - s * CIN;
                    pa[j] = act4(*reinterpret_cast<const float4*>(src + sidx[m][s] + c), c);
                }
#pragma unroll
                for (int j = 0; j < NBB; j++) {
                    int i = tid + j * 256;
                    int n = i >> 2, kq = i & 3;
                    pbv[j] = *reinterpret_cast<const float4*>(
                        w + (size_t)(n0 + n) * K + kn + kq * 4);
                }
            }

            // ---- compute current tile from SMEM ----
#pragma unroll
            for (int kk = 0; kk < BK; kk++) {
                float a[8], bb[TN];
                {
                    float4 a0 = *reinterpret_cast<const float4*>(&As[kk * AS_STRIDE + ty * 4]);
                    float4 a1 = *reinterpret_cast<const float4*>(&As[kk * AS_STRIDE + 64 + ty * 4]);
                    a[0] = a0.x; a[1] = a0.y; a[2] = a0.z; a[3] = a0.w;
                    a[4] = a1.x; a[5] = a1.y; a[6] = a1.z; a[7] = a1.w;
                }
#pragma unroll
                for (int t = 0; t < TG; t++) {
                    float4 b4 = *reinterpret_cast<const float4*>(&Bs[kk * BNT + t * 64 + tx * 4]);
                    bb[t * 4 + 0] = b4.x; bb[t * 4 + 1] = b4.y;
                    bb[t * 4 + 2] = b4.z; bb[t * 4 + 3] = b4.w;
                }
#pragma unroll
                for (int i = 0; i < 8; i++)
#pragma unroll
                    for (int j = 0; j < TN; j++)
                        acc[i][j] += a[i] * bb[j];
            }
            __syncthreads();
        }
    } else {
        // ---------------- simple mainloop (L1, K = 27) ----------------
        for (int k0 = 0; k0 < K; k0 += BK) {
#pragma unroll
            for (int j = 0; j < 8; j++) {
                int i = tid + j * 256;          // 0..2047
                int m = i & 127, k = i >> 7;
                int kk = k0 + k;
                float v = 0.f;
                if (kk < K) {
                    int s = kk / CIN, c = kk - s * CIN;
                    v = src[sidx[m][s] + c];
                }
                As[k * AS_STRIDE + m] = v;
            }
#pragma unroll
            for (int j = 0; j < (BK * BNT) / 256; j++) {
                int i = tid + j * 256;
                int n = i & (BNT - 1), k = i / BNT;
                int kk = k0 + k;
                float v = 0.f;
                if (kk < K) v = w[(size_t)(n0 + n) * K + kk];
                Bs[k * BNT + n] = v;
            }
            __syncthreads();

#pragma unroll
            for (int kk = 0; kk < BK; kk++) {
                float a[8], bb[TN];
                {
                    float4 a0 = *reinterpret_cast<const float4*>(&As[kk * AS_STRIDE + ty * 4]);
                    float4 a1 = *reinterpret_cast<const float4*>(&As[kk * AS_STRIDE + 64 + ty * 4]);
                    a[0] = a0.x; a[1] = a0.y; a[2] = a0.z; a[3] = a0.w;
                    a[4] = a1.x; a[5] = a1.y; a[6] = a1.z; a[7] = a1.w;
                }
#pragma unroll
                for (int t = 0; t < TG; t++) {
                    float4 b4 = *reinterpret_cast<const float4*>(&Bs[kk * BNT + t * 64 + tx * 4]);
                    bb[t * 4 + 0] = b4.x; bb[t * 4 + 1] = b4.y;
                    bb[t * 4 + 2] = b4.z; bb[t * 4 + 3] = b4.w;
                }
#pragma unroll
                for (int i = 0; i < 8; i++)
#pragma unroll
                    for (int j = 0; j < TN; j++)
                        acc[i][j] += a[i] * bb[j];
            }
            __syncthreads();
        }
    }

    // ---- Store output tile (no bias: it cancels in BatchNorm) ----
#pragma unroll
    for (int i = 0; i < 8; i++) {
        int m = m0 + ((i < 4) ? (ty * 4 + i) : (64 + ty * 4 + (i - 4)));
#pragma unroll
        for (int t = 0; t < TG; t++) {
            float4 o;
            o.x = acc[i][t * 4 + 0];
            o.y = acc[i][t * 4 + 1];
            o.z = acc[i][t * 4 + 2];
            o.w = acc[i][t * 4 + 3];
            *reinterpret_cast<float4*>(&y[(size_t)m * N + n0 + t * 64 + tx * 4]) = o;
        }
    }

    // ---- Fused BN statistics: per-block column sum / sumsq partials ----
    {
        float s[TN], q[TN];
#pragma unroll
        for (int j = 0; j < TN; j++) { s[j] = 0.f; q[j] = 0.f; }
#pragma unroll
        for (int i = 0; i < 8; i++)
#pragma unroll
            for (int j = 0; j < TN; j++) {
                float v = acc[i][j];
                s[j] += v;
                q[j] += v * v;
            }
        float* ssum = As;   // 16 * BNT floats fits in As (16 * 132)
        float* ssq  = Bs;   // 16 * BNT floats == Bs size
#pragma unroll
        for (int t = 0; t < TG; t++)
#pragma unroll
            for (int j = 0; j < 4; j++) {
                int col = t * 64 + tx * 4 + j;
                ssum[ty * BNT + col] = s[t * 4 + j];
                ssq [ty * BNT + col] = q[t * 4 + j];
            }
        __syncthreads();
        if (tid < BNT) {
            float S = 0.f, Q = 0.f;
#pragma unroll
            for (int r = 0; r < 16; r++) {
                S += ssum[r * BNT + tid];
                Q += ssq [r * BNT + tid];
            }
            psum[(size_t)blockIdx.x * N + n0 + tid] = S;
            psq [(size_t)blockIdx.x * N + n0 + tid] = Q;
        }
    }
}

// ---------------------------------------------------------------------------
// Reduce per-block partials -> BN scale/shift (fp64, deterministic)
// ---------------------------------------------------------------------------
__global__ void finalize_kernel(const float* __restrict__ psum,
                                const float* __restrict__ psq,
                                const float* __restrict__ g,
                                const float* __restrict__ bt,
                                float* __restrict__ scale,
                                float* __restrict__ shift, int N) {
    int o = threadIdx.x;
    if (o >= N) return;
    double s = 0.0, q = 0.0;
    for (int c = 0; c < NPART; c++) {
        s += psum[(size_t)c * N + o];
        q += psq [(size_t)c * N + o];
    }
    double mean = s / (double)MTOT;
    double var  = q / (double)MTOT - mean * mean;   // biased variance (ddof=0)
    float sc = g[o] * rsqrtf((float)var + 1e-5f);
    scale[o] = sc;
    shift[o] = bt[o] - (float)mean * sc;
}

// Max over vertices with fused BN+ReLU: grid (256/32, B), block (32, 8)
// relu(max(affine)) == max(relu(affine)) since relu is monotone.
__global__ void maxpool_kernel(const float* __restrict__ act,
                               const float* __restrict__ scale,
                               const float* __restrict__ shift,
                               float* __restrict__ hmax) {
    const int tx = threadIdx.x, ty = threadIdx.y;
    const int o = blockIdx.x * 32 + tx;
    const int b = blockIdx.y;
    const float sc = scale[o], sh = shift[o];
    float m = -1e30f;
    for (int v = ty; v < NV; v += 8)
        m = fmaxf(m, fmaf(act[((size_t)b * NV + v) * 256 + o], sc, sh));
    __shared__ float shm[8][32];
    shm[ty][tx] = m;
    __syncthreads();
    if (ty == 0) {
#pragma unroll
        for (int i = 1; i < 8; i++) m = fmaxf(m, shm[i][tx]);
        hmax[b * 256 + o] = fmaxf(m, 0.f);
    }
}

// out[b, j] = sum_o hmax[b, o] * pw[j, o] + pb[j]
__global__ void final_linear_kernel(const float* __restrict__ hmax,
                                    const float* __restrict__ pw,
                                    const float* __restrict__ pb,
                                    float* __restrict__ out) {
    __shared__ float sh[BATCH * 256];
    for (int i = threadIdx.x; i < BATCH * 256; i += 256) sh[i] = hmax[i];
    __syncthreads();
    int j = threadIdx.x;
    float acc[BATCH];
#pragma unroll
    for (int b = 0; b < BATCH; b++) acc[b] = pb[j];
    for (int o = 0; o < 256; o++) {
        float wv = pw[j * 256 + o];
#pragma unroll
        for (int b = 0; b < BATCH; b++) acc[b] += sh[b * 256 + o] * wv;
    }
#pragma unroll
    for (int b = 0; b < BATCH; b++) out[b * 256 + j] = acc[b];
}

// ---------------------------------------------------------------------------
extern "C" void kernel_launch(void* const* d_in, const int* in_sizes, int n_in,
                              void* d_out, int out_size) {
    const float* x    = (const float*)d_in[0];
    const void*  spir = d_in[1];
    const float* w1 = (const float*)d_in[2];
    const float* g1 = (const float*)d_in[4];
    const float* t1 = (const float*)d_in[5];
    const float* w2 = (const float*)d_in[6];
    const float* g2 = (const float*)d_in[8];
    const float* t2 = (const float*)d_in[9];
    const float* w3 = (const float*)d_in[10];
    const float* g3 = (const float*)d_in[12];
    const float* t3 = (const float*)d_in[13];
    const float* pw = (const float*)d_in[14];
    const float* pb = (const float*)d_in[15];

    float *bufA, *bufB, *psum, *psq, *scale, *shift, *hmax;
    cudaGetSymbolAddress((void**)&bufA,  g_bufA);
    cudaGetSymbolAddress((void**)&bufB,  g_bufB);
    cudaGetSymbolAddress((void**)&psum,  g_psum);
    cudaGetSymbolAddress((void**)&psq,   g_psq);
    cudaGetSymbolAddress((void**)&scale, g_scale);
    cudaGetSymbolAddress((void**)&shift, g_shift);
    cudaGetSymbolAddress((void**)&hmax,  g_hmax);

    detect64_kernel<<<1, 256>>>((const long long*)spir);

    const int mblocks = MTOT / BM;   // 750

    // ---- Layer 1: 3 -> 64 (K = 27), raw input ----
    gemm_gather_kernel<3, false, 64, false><<<dim3(mblocks, 1), 256>>>(
        x, spir, w1, nullptr, nullptr, bufA, psum, psq, 64);
    finalize_kernel<<<1, 64>>>(psum, psq, g1, t1, scale, shift, 64);

    // ---- Layer 2: 64 -> 128 (K = 576), BN1+ReLU fused into gather ----
    gemm_gather_kernel<64, true, 128, true><<<dim3(mblocks, 1), 256>>>(
        bufA, spir, w2, scale, shift, bufB, psum, psq, 128);
    finalize_kernel<<<1, 128>>>(psum, psq, g2, t2, scale, shift, 128);

    // ---- Layer 3: 128 -> 256 (K = 1152), BN2+ReLU fused into gather ----
    gemm_gather_kernel<128, true, 128, true><<<dim3(mblocks, 2), 256>>>(
        bufB, spir, w3, scale, shift, bufA, psum, psq, 256);
    finalize_kernel<<<1, 256>>>(psum, psq, g3, t3, scale, shift, 256);

    // ---- Max pool (BN3+ReLU fused) + final linear ----
    maxpool_kernel<<<dim3(8, BATCH), dim3(32, 8)>>>(bufA, scale, shift, hmax);
    final_linear_kernel<<<1, 256>>>(hmax, pw, pb, (float*)d_out);
}

// round 5
// speedup vs baseline: 1.1663x; 1.1663x over previous
#include <cuda_runtime.h>
#include <cuda_bf16.h>
#include <cstdint>
#include <cstddef>

// Problem constants
#define BATCH 8
#define NV    12000
#define NS    9
#define MTOT  (BATCH * NV)   // 96000
#define NPART (MTOT / 128)   // 750 m-blocks -> stats partials per layer

// Scratch (device globals; no allocation allowed)
__device__ float g_bufA[(size_t)MTOT * 256];   // 98.3 MB
__device__ float g_bufB[(size_t)MTOT * 128];   // 49.2 MB
__device__ float g_psum[NPART * 256];
__device__ float g_psq [NPART * 256];
__device__ float g_scale[256];
__device__ float g_shift[256];
__device__ float g_hmax[BATCH * 256];
__device__ int   g_is64;

// ---------------------------------------------------------------------------
// Detect whether the spiral index tensor is int64 or int32.
// ---------------------------------------------------------------------------
__global__ void detect64_kernel(const long long* __restrict__ p) {
    bool ok = true;
    for (int i = threadIdx.x; i < 2048; i += 256) {
        long long v = p[i];
        if (v < 0 || v >= NV) ok = false;
    }
    int all = __syncthreads_and(ok ? 1 : 0);
    if (threadIdx.x == 0) g_is64 = all;
}

// ---------------------------------------------------------------------------
// Gather-fused SGEMM with fused BN-apply on input (NORM) and fused BN stats
// on output: y[m, n] = sum_k act(feat)[m, k] * w[n, k]
// act(v) = NORM ? relu(v * scale[c] + shift[c]) : v
// Conv bias dropped: BatchNorm's mean subtraction cancels it exactly.
// Tiling: BM=128, BNT in {64,128}, BK=16; 256 threads; 8 x (BNT/16) microtile.
// __launch_bounds__(256, 2): cap regs at 128 so 2 CTAs/SM co-reside and
// cover each other's barrier + global-load latency (R4 ncu: occ was 12.5%,
// fma 47.5% with 167 regs / 1 CTA per SM).
// ---------------------------------------------------------------------------
#define BM 128
#define BK 16
#define AS_STRIDE (BM + 4)   // 132: 16B-aligned rows, reduced STS conflicts

template <int CIN, bool VEC, int BNT, bool NORM>
__global__ __launch_bounds__(256, 2)
void gemm_gather_kernel(const float* __restrict__ src,
                        const void* __restrict__ spir_raw,
                        const float* __restrict__ w,
                        const float* __restrict__ scale,
                        const float* __restrict__ shift,
                        float* __restrict__ y,
                        float* __restrict__ psum,
                        float* __restrict__ psq,
                        int N) {
    constexpr int K   = NS * CIN;
    constexpr int TN  = BNT / 16;        // columns per thread (4 or 8)
    constexpr int TG  = TN / 4;          // float4 groups per thread
    constexpr int NBB = (BK * BNT) / (4 * 256);  // B float4s per thread (1 or 2)
    __shared__ float As[BK * AS_STRIDE];
    __shared__ float Bs[BK * BNT];
    __shared__ int   sidx[BM][NS];       // pre-scaled row base: (b*NV + idx)*CIN
    __shared__ __align__(16) float s_sc[CIN];
    __shared__ __align__(16) float s_sh[CIN];

    const int tid = threadIdx.x;
    const int tx = tid & 15;             // n-dim
    const int ty = tid >> 4;             // m-dim
    const int m0 = blockIdx.x * BM;
    const int n0 = blockIdx.y * BNT;

    // Stage BN params for the input activation
    if constexpr (NORM) {
        for (int i = tid; i < CIN; i += 256) {
            s_sc[i] = scale[i];
            s_sh[i] = shift[i];
        }
    }

    // Resolve spiral indices for this row tile
    {
        const long long* s64 = (const long long*)spir_raw;
        const int*       s32 = (const int*)spir_raw;
        const int is64 = g_is64;
        for (int j = tid; j < BM * NS; j += 256) {
            int m = j / NS, s = j - m * NS;
            int gm = m0 + m;
            int b = gm / NV;
            long long e = is64 ? s64[(size_t)gm * NS + s]
                               : (long long)s32[(size_t)gm * NS + s];
            sidx[m][s] = (b * NV + (int)e) * CIN;
        }
    }
    __syncthreads();

    // Apply BN + ReLU to a gathered float4 at channel base c (c % 4 == 0)
    auto act4 = [&](float4 v, int c) -> float4 {
        if constexpr (NORM) {
            float4 sc4 = *reinterpret_cast<const float4*>(&s_sc[c]);
            float4 sh4 = *reinterpret_cast<const float4*>(&s_sh[c]);
            v.x = fmaxf(fmaf(v.x, sc4.x, sh4.x), 0.f);
            v.y = fmaxf(fmaf(v.y, sc4.y, sh4.y), 0.f);
            v.z = fmaxf(fmaf(v.z, sc4.z, sh4.z), 0.f);
            v.w = fmaxf(fmaf(v.w, sc4.w, sh4.w), 0.f);
        }
        return v;
    };

    float acc[8][TN];
#pragma unroll
    for (int i = 0; i < 8; i++)
#pragma unroll
        for (int j = 0; j < TN; j++) acc[i][j] = 0.f;

    if constexpr (VEC) {
        // ---------------- software-pipelined mainloop ----------------
        float4 pa[2], pbv[NBB];

        // prefetch k0 = 0
        {
#pragma unroll
            for (int j = 0; j < 2; j++) {
                int i = tid + j * 256;       // 0..511
                int m = i >> 2, kq = i & 3;
                int k = kq * 4;
                int s = k / CIN, c = k - s * CIN;
                pa[j] = act4(*reinterpret_cast<const float4*>(src + sidx[m][s] + c), c);
            }
#pragma unroll
            for (int j = 0; j < NBB; j++) {
                int i = tid + j * 256;
                int n = i >> 2, kq = i & 3;
                pbv[j] = *reinterpret_cast<const float4*>(
                    w + (size_t)(n0 + n) * K + kq * 4);
            }
        }

        for (int k0 = 0; k0 < K; k0 += BK) {
            // ---- store staged tile to SMEM ----
#pragma unroll
            for (int j = 0; j < 2; j++) {
                int i = tid + j * 256;
                int m = i >> 2, kq = i & 3;
                As[(kq * 4 + 0) * AS_STRIDE + m] = pa[j].x;
                As[(kq * 4 + 1) * AS_STRIDE + m] = pa[j].y;
                As[(kq * 4 + 2) * AS_STRIDE + m] = pa[j].z;
                As[(kq * 4 + 3) * AS_STRIDE + m] = pa[j].w;
            }
#pragma unroll
            for (int j = 0; j < NBB; j++) {
                int i = tid + j * 256;
                int n = i >> 2, kq = i & 3;
                Bs[(kq * 4 + 0) * BNT + n] = pbv[j].x;
                Bs[(kq * 4 + 1) * BNT + n] = pbv[j].y;
                Bs[(kq * 4 + 2) * BNT + n] = pbv[j].z;
                Bs[(kq * 4 + 3) * BNT + n] = pbv[j].w;
            }
            __syncthreads();

            // ---- issue next tile's global loads (fly under compute) ----
            const int kn = k0 + BK;
            if (kn < K) {
#pragma unroll
                for (int j = 0; j < 2; j++) {
                    int i = tid + j * 256;
                    int m = i >> 2, kq = i & 3;
                    int k = kn + kq * 4;
                    int s = k / CIN, c = k - s * CIN;
                    pa[j] = act4(*reinterpret_cast<const float4*>(src + sidx[m][s] + c), c);
                }
#pragma unroll
                for (int j = 0; j < NBB; j++) {
                    int i = tid + j * 256;
                    int n = i >> 2, kq = i & 3;
                    pbv[j] = *reinterpret_cast<const float4*>(
                        w + (size_t)(n0 + n) * K + kn + kq * 4);
                }
            }

            // ---- compute current tile from SMEM ----
#pragma unroll
            for (int kk = 0; kk < BK; kk++) {
                float a[8], bb[TN];
                {
                    float4 a0 = *reinterpret_cast<const float4*>(&As[kk * AS_STRIDE + ty * 4]);
                    float4 a1 = *reinterpret_cast<const float4*>(&As[kk * AS_STRIDE + 64 + ty * 4]);
                    a[0] = a0.x; a[1] = a0.y; a[2] = a0.z; a[3] = a0.w;
                    a[4] = a1.x; a[5] = a1.y; a[6] = a1.z; a[7] = a1.w;
                }
#pragma unroll
                for (int t = 0; t < TG; t++) {
                    float4 b4 = *reinterpret_cast<const float4*>(&Bs[kk * BNT + t * 64 + tx * 4]);
                    bb[t * 4 + 0] = b4.x; bb[t * 4 + 1] = b4.y;
                    bb[t * 4 + 2] = b4.z; bb[t * 4 + 3] = b4.w;
                }
#pragma unroll
                for (int i = 0; i < 8; i++)
#pragma unroll
                    for (int j = 0; j < TN; j++)
                        acc[i][j] += a[i] * bb[j];
            }
            __syncthreads();
        }
    } else {
        // ---------------- simple mainloop (L1, K = 27) ----------------
        for (int k0 = 0; k0 < K; k0 += BK) {
#pragma unroll
            for (int j = 0; j < 8; j++) {
                int i = tid + j * 256;          // 0..2047
                int m = i & 127, k = i >> 7;
                int kk = k0 + k;
                float v = 0.f;
                if (kk < K) {
                    int s = kk / CIN, c = kk - s * CIN;
                    v = src[sidx[m][s] + c];
                }
                As[k * AS_STRIDE + m] = v;
            }
#pragma unroll
            for (int j = 0; j < (BK * BNT) / 256; j++) {
                int i = tid + j * 256;
                int n = i & (BNT - 1), k = i / BNT;
                int kk = k0 + k;
                float v = 0.f;
                if (kk < K) v = w[(size_t)(n0 + n) * K + kk];
                Bs[k * BNT + n] = v;
            }
            __syncthreads();

#pragma unroll
            for (int kk = 0; kk < BK; kk++) {
                float a[8], bb[TN];
                {
                    float4 a0 = *reinterpret_cast<const float4*>(&As[kk * AS_STRIDE + ty * 4]);
                    float4 a1 = *reinterpret_cast<const float4*>(&As[kk * AS_STRIDE + 64 + ty * 4]);
                    a[0] = a0.x; a[1] = a0.y; a[2] = a0.z; a[3] = a0.w;
                    a[4] = a1.x; a[5] = a1.y; a[6] = a1.z; a[7] = a1.w;
                }
#pragma unroll
                for (int t = 0; t < TG; t++) {
                    float4 b4 = *reinterpret_cast<const float4*>(&Bs[kk * BNT + t * 64 + tx * 4]);
                    bb[t * 4 + 0] = b4.x; bb[t * 4 + 1] = b4.y;
                    bb[t * 4 + 2] = b4.z; bb[t * 4 + 3] = b4.w;
                }
#pragma unroll
                for (int i = 0; i < 8; i++)
#pragma unroll
                    for (int j = 0; j < TN; j++)
                        acc[i][j] += a[i] * bb[j];
            }
            __syncthreads();
        }
    }

    // ---- Store output tile (no bias: it cancels in BatchNorm) ----
#pragma unroll
    for (int i = 0; i < 8; i++) {
        int m = m0 + ((i < 4) ? (ty * 4 + i) : (64 + ty * 4 + (i - 4)));
#pragma unroll
        for (int t = 0; t < TG; t++) {
            float4 o;
            o.x = acc[i][t * 4 + 0];
            o.y = acc[i][t * 4 + 1];
            o.z = acc[i][t * 4 + 2];
            o.w = acc[i][t * 4 + 3];
            *reinterpret_cast<float4*>(&y[(size_t)m * N + n0 + t * 64 + tx * 4]) = o;
        }
    }

    // ---- Fused BN statistics: per-block column sum / sumsq partials ----
    {
        float s[TN], q[TN];
#pragma unroll
        for (int j = 0; j < TN; j++) { s[j] = 0.f; q[j] = 0.f; }
#pragma unroll
        for (int i = 0; i < 8; i++)
#pragma unroll
            for (int j = 0; j < TN; j++) {
                float v = acc[i][j];
                s[j] += v;
                q[j] += v * v;
            }
        float* ssum = As;   // 16 * BNT floats fits in As (16 * 132)
        float* ssq  = Bs;   // 16 * BNT floats == Bs size
#pragma unroll
        for (int t = 0; t < TG; t++)
#pragma unroll
            for (int j = 0; j < 4; j++) {
                int col = t * 64 + tx * 4 + j;
                ssum[ty * BNT + col] = s[t * 4 + j];
                ssq [ty * BNT + col] = q[t * 4 + j];
            }
        __syncthreads();
        if (tid < BNT) {
            float S = 0.f, Q = 0.f;
#pragma unroll
            for (int r = 0; r < 16; r++) {
                S += ssum[r * BNT + tid];
                Q += ssq [r * BNT + tid];
            }
            psum[(size_t)blockIdx.x * N + n0 + tid] = S;
            psq [(size_t)blockIdx.x * N + n0 + tid] = Q;
        }
    }
}

// ---------------------------------------------------------------------------
// Reduce per-block partials -> BN scale/shift (fp64, deterministic)
// ---------------------------------------------------------------------------
__global__ void finalize_kernel(const float* __restrict__ psum,
                                const float* __restrict__ psq,
                                const float* __restrict__ g,
                                const float* __restrict__ bt,
                                float* __restrict__ scale,
                                float* __restrict__ shift, int N) {
    int o = threadIdx.x;
    if (o >= N) return;
    double s = 0.0, q = 0.0;
    for (int c = 0; c < NPART; c++) {
        s += psum[(size_t)c * N + o];
        q += psq [(size_t)c * N + o];
    }
    double mean = s / (double)MTOT;
    double var  = q / (double)MTOT - mean * mean;   // biased variance (ddof=0)
    float sc = g[o] * rsqrtf((float)var + 1e-5f);
    scale[o] = sc;
    shift[o] = bt[o] - (float)mean * sc;
}

// Max over vertices with fused BN+ReLU: grid (256/32, B), block (32, 8)
__global__ void maxpool_kernel(const float* __restrict__ act,
                               const float* __restrict__ scale,
                               const float* __restrict__ shift,
                               float* __restrict__ hmax) {
    const int tx = threadIdx.x, ty = threadIdx.y;
    const int o = blockIdx.x * 32 + tx;
    const int b = blockIdx.y;
    const float sc = scale[o], sh = shift[o];
    float m = -1e30f;
    for (int v = ty; v < NV; v += 8)
        m = fmaxf(m, fmaf(act[((size_t)b * NV + v) * 256 + o], sc, sh));
    __shared__ float shm[8][32];
    shm[ty][tx] = m;
    __syncthreads();
    if (ty == 0) {
#pragma unroll
        for (int i = 1; i < 8; i++) m = fmaxf(m, shm[i][tx]);
        hmax[b * 256 + o] = fmaxf(m, 0.f);
    }
}

// out[b, j] = sum_o hmax[b, o] * pw[j, o] + pb[j]
__global__ void final_linear_kernel(const float* __restrict__ hmax,
                                    const float* __restrict__ pw,
                                    const float* __restrict__ pb,
                                    float* __restrict__ out) {
    __shared__ float sh[BATCH * 256];
    for (int i = threadIdx.x; i < BATCH * 256; i += 256) sh[i] = hmax[i];
    __syncthreads();
    int j = threadIdx.x;
    float acc[BATCH];
#pragma unroll
    for (int b = 0; b < BATCH; b++) acc[b] = pb[j];
    for (int o = 0; o < 256; o++) {
        float wv = pw[j * 256 + o];
#pragma unroll
        for (int b = 0; b < BATCH; b++) acc[b] += sh[b * 256 + o] * wv;
    }
#pragma unroll
    for (int b = 0; b < BATCH; b++) out[b * 256 + j] = acc[b];
}

// ---------------------------------------------------------------------------
extern "C" void kernel_launch(void* const* d_in, const int* in_sizes, int n_in,
                              void* d_out, int out_size) {
    const float* x    = (const float*)d_in[0];
    const void*  spir = d_in[1];
    const float* w1 = (const float*)d_in[2];
    const float* g1 = (const float*)d_in[4];
    const float* t1 = (const float*)d_in[5];
    const float* w2 = (const float*)d_in[6];
    const float* g2 = (const float*)d_in[8];
    const float* t2 = (const float*)d_in[9];
    const float* w3 = (const float*)d_in[10];
    const float* g3 = (const float*)d_in[12];
    const float* t3 = (const float*)d_in[13];
    const float* pw = (const float*)d_in[14];
    const float* pb = (const float*)d_in[15];

    float *bufA, *bufB, *psum, *psq, *scale, *shift, *hmax;
    cudaGetSymbolAddress((void**)&bufA,  g_bufA);
    cudaGetSymbolAddress((void**)&bufB,  g_bufB);
    cudaGetSymbolAddress((void**)&psum,  g_psum);
    cudaGetSymbolAddress((void**)&psq,   g_psq);
    cudaGetSymbolAddress((void**)&scale, g_scale);
    cudaGetSymbolAddress((void**)&shift, g_shift);
    cudaGetSymbolAddress((void**)&hmax,  g_hmax);

    detect64_kernel<<<1, 256>>>((const long long*)spir);

    const int mblocks = MTOT / BM;   // 750

    // ---- Layer 1: 3 -> 64 (K = 27), raw input ----
    gemm_gather_kernel<3, false, 64, false><<<dim3(mblocks, 1), 256>>>(
        x, spir, w1, nullptr, nullptr, bufA, psum, psq, 64);
    finalize_kernel<<<1, 64>>>(psum, psq, g1, t1, scale, shift, 64);

    // ---- Layer 2: 64 -> 128 (K = 576), BN1+ReLU fused into gather ----
    gemm_gather_kernel<64, true, 128, true><<<dim3(mblocks, 1), 256>>>(
        bufA, spir, w2, scale, shift, bufB, psum, psq, 128);
    finalize_kernel<<<1, 128>>>(psum, psq, g2, t2, scale, shift, 128);

    // ---- Layer 3: 128 -> 256 (K = 1152), BN2+ReLU fused into gather ----
    gemm_gather_kernel<128, true, 128, true><<<dim3(mblocks, 2), 256>>>(
        bufB, spir, w3, scale, shift, bufA, psum, psq, 256);
    finalize_kernel<<<1, 256>>>(psum, psq, g3, t3, scale, shift, 256);

    // ---- Max pool (BN3+ReLU fused) + final linear ----
    maxpool_kernel<<<dim3(8, BATCH), dim3(32, 8)>>>(bufA, scale, shift, hmax);
    final_linear_kernel<<<1, 256>>>(hmax, pw, pb, (float*)d_out);
}